// round 4
// baseline (speedup 1.0000x reference)
#include <cuda_runtime.h>

#define Bb   8
#define Nn   1024
#define Ee   1536
#define FI   64
#define FO   64
#define FE   32

// ---- scratch (device globals; no allocation allowed) ----
// Endpoint arrays use idempotent atomicMax encodings so the load-time
// zero-init is a valid neutral element and graph replays are stable:
//   g_epmax[e]  = max endpoint  (true max >= 1 since endpoints distinct)
//   g_epneg[e]  = max(N-1 - i)  -> min endpoint = N-1 - g_epneg[e] (>=1 since min<=N-2)
__device__ int   g_epmax[Ee];
__device__ int   g_epneg[Ee];
__device__ float g_diagsum[Bb * Nn];          // zeroed each launch, atomicAdd'ed
__device__ float g_coef[Bb * Ee];             // lap[s,d] * ew[b,e]
__device__ float g_h[Bb * Nn * FO];           // nodes @ W

// K0: zero the per-launch accumulator
__global__ void k_zero_diag() {
    int i = blockIdx.x * blockDim.x + threadIdx.x;
    if (i < Bb * Nn) g_diagsum[i] = 0.0f;
}

// K1: scan inc [N,E] (row-major), record the two endpoints of each edge.
// Coalesced float4 reads; only ~3072 atomics fire.
__global__ void __launch_bounds__(256) k_scan_inc(const float* __restrict__ inc) {
    int idx4 = blockIdx.x * blockDim.x + threadIdx.x;     // exact: N*E/4 threads
    float4 v = reinterpret_cast<const float4*>(inc)[idx4];
    int base = idx4 * 4;
    float a[4] = {v.x, v.y, v.z, v.w};
#pragma unroll
    for (int k = 0; k < 4; k++) {
        if (a[k] != 0.0f) {
            int lin = base + k;
            int e = lin % Ee;
            int i = lin / Ee;
            atomicMax(&g_epmax[e], i);
            atomicMax(&g_epneg[e], (Nn - 1) - i);
        }
    }
}

// K2: one warp per (b,e): ew = edges[b,e,:] . evec (FE==32 -> one lane each),
// then coef[b,e] = lap[s,d]*ew and diagonal accumulation at both endpoints.
__global__ void __launch_bounds__(256) k_edge(const float* __restrict__ edges,
                                              const float* __restrict__ evec,
                                              const float* __restrict__ lap) {
    int w    = (blockIdx.x * blockDim.x + threadIdx.x) >> 5;   // b*E + e
    int lane = threadIdx.x & 31;
    float p = edges[(size_t)w * FE + lane] * evec[lane];
#pragma unroll
    for (int o = 16; o; o >>= 1) p += __shfl_xor_sync(0xffffffffu, p, o);
    if (lane == 0) {
        int e = w % Ee;
        int b = w / Ee;
        int d = g_epmax[e];
        int s = (Nn - 1) - g_epneg[e];
        g_coef[w] = lap[(size_t)s * Nn + d] * p;
        atomicAdd(&g_diagsum[b * Nn + s], p);
        atomicAdd(&g_diagsum[b * Nn + d], p);
    }
}

// K3: h = nodes @ W. 64x64 output tile per 256-thread block; 4x4 micro-tile
// per thread with float4 smem reads (A stored k-major/transposed).
__global__ void __launch_bounds__(256) k_gemm(const float* __restrict__ nodes,
                                              const float* __restrict__ W) {
    __shared__ float sW[FI][FO];     // W[k][c]
    __shared__ float sA[FI][64];     // nodes^T: sA[k][r]
    int row0 = blockIdx.x * 64;      // flattened rows b*N+i, 8192 total
    int t = threadIdx.x;

    // load W (4096 floats = 1024 float4)
    for (int i = t; i < FI * FO / 4; i += 256)
        reinterpret_cast<float4*>(&sW[0][0])[i] =
            reinterpret_cast<const float4*>(W)[i];

    // load + transpose 64 node rows
    for (int i = t; i < 64 * FI / 4; i += 256) {
        int r  = i / (FI / 4);
        int k4 = (i % (FI / 4)) * 4;
        float4 v = reinterpret_cast<const float4*>(
            nodes + (size_t)(row0 + r) * FI + k4)[0];
        sA[k4 + 0][r] = v.x; sA[k4 + 1][r] = v.y;
        sA[k4 + 2][r] = v.z; sA[k4 + 3][r] = v.w;
    }
    __syncthreads();

    int tr = (t >> 4) << 2;          // row offset in tile (0..60)
    int tc = (t & 15) << 2;          // col offset in tile (0..60)
    float acc[4][4] = {};
#pragma unroll
    for (int k = 0; k < FI; k++) {
        float4 a  = *reinterpret_cast<const float4*>(&sA[k][tr]);
        float4 bv = *reinterpret_cast<const float4*>(&sW[k][tc]);
        float av[4] = {a.x, a.y, a.z, a.w};
        float bb[4] = {bv.x, bv.y, bv.z, bv.w};
#pragma unroll
        for (int i = 0; i < 4; i++)
#pragma unroll
            for (int j = 0; j < 4; j++)
                acc[i][j] = fmaf(av[i], bb[j], acc[i][j]);
    }
#pragma unroll
    for (int i = 0; i < 4; i++) {
        float4 o = {acc[i][0], acc[i][1], acc[i][2], acc[i][3]};
        reinterpret_cast<float4*>(&g_h[(size_t)(row0 + tr + i) * FO + tc])[0] = o;
    }
}

// K4: out = (lap[i,i] * diagsum[b,i]) * h[b,i,:]  — plain stores (clears poison,
// zeroes isolated-node rows) before the atomic scatter.
__global__ void __launch_bounds__(256) k_outinit(const float* __restrict__ lap,
                                                 float* __restrict__ out) {
    int idx = blockIdx.x * blockDim.x + threadIdx.x;   // over B*N*FO/4
    int bn = idx >> 4;                                 // FO/4 = 16
    int i  = bn & (Nn - 1);
    float dc = g_diagsum[bn] * lap[(size_t)i * (Nn + 1)];
    float4 h4 = reinterpret_cast<const float4*>(g_h)[idx];
    float4 o = {dc * h4.x, dc * h4.y, dc * h4.z, dc * h4.w};
    reinterpret_cast<float4*>(out)[idx] = o;
}

// K5: per-edge scatter: out[b,s,:] += coef * h[b,d,:]  and symmetric.
// One warp per (b,e); 64 floats per row -> float2 per lane, coalesced REDs.
__global__ void __launch_bounds__(256) k_scatter(float* __restrict__ out) {
    int w    = (blockIdx.x * blockDim.x + threadIdx.x) >> 5;   // b*E + e
    int lane = threadIdx.x & 31;
    int e = w % Ee;
    int b = w / Ee;
    float c = g_coef[w];
    int d = g_epmax[e];
    int s = (Nn - 1) - g_epneg[e];
    const float2* hs = reinterpret_cast<const float2*>(&g_h[((size_t)b * Nn + s) * FO]);
    const float2* hd = reinterpret_cast<const float2*>(&g_h[((size_t)b * Nn + d) * FO]);
    float2 vs = hs[lane];
    float2 vd = hd[lane];
    float* os = &out[((size_t)b * Nn + s) * FO + 2 * lane];
    float* od = &out[((size_t)b * Nn + d) * FO + 2 * lane];
    atomicAdd(os + 0, c * vd.x);
    atomicAdd(os + 1, c * vd.y);
    atomicAdd(od + 0, c * vs.x);
    atomicAdd(od + 1, c * vs.y);
}

extern "C" void kernel_launch(void* const* d_in, const int* in_sizes, int n_in,
                              void* d_out, int out_size) {
    const float* nodes = (const float*)d_in[0];   // [B,N,64]
    const float* edges = (const float*)d_in[1];   // [B,E,32]
    const float* Wm    = (const float*)d_in[2];   // [64,64]
    const float* evec  = (const float*)d_in[3];   // [32]
    const float* inc   = (const float*)d_in[4];   // [N,E]
    const float* lap   = (const float*)d_in[5];   // [N,N]
    float*       out   = (float*)d_out;           // [B,N,64]

    k_zero_diag<<<(Bb * Nn + 255) / 256, 256>>>();
    k_scan_inc<<<(Nn * Ee / 4) / 256, 256>>>(inc);              // 1536 blocks
    k_gemm<<<(Bb * Nn) / 64, 256>>>(nodes, Wm);                 // 128 blocks
    k_edge<<<(Bb * Ee * 32) / 256, 256>>>(edges, evec, lap);    // 1536 blocks
    k_outinit<<<(Bb * Nn * FO / 4) / 256, 256>>>(lap, out);     // 512 blocks
    k_scatter<<<(Bb * Ee * 32) / 256, 256>>>(out);              // 1536 blocks
}